// round 14
// baseline (speedup 1.0000x reference)
#include <cuda_runtime.h>
#include <math.h>

#define B    32
#define NP   100
#define F_IN 36
#define FC   40
#define KNN  11
#define GDIM 440
#define H    3600
#define NLAY 5
#define EPSB 0.001f
#define SPLITK 10
#define TILEK  32
#define NCOLS  64
#define NBX    57

typedef unsigned long long u64;

// ---------------- device scratch ----------------
__device__ float d_xfeat[B*NP*FC];
__device__ float d_g[B*GDIM];
__device__ float d_hA[B*H];
__device__ float d_hB[B*H];
__device__ float d_c2[B*2];
// row-pair packed partials: [kb][rowpair(16)][H], entry = (row2rp, row2rp+1)
__device__ u64 d_pS[SPLITK*16*H];
__device__ u64 d_pC[SPLITK*16*H];   // NC (negated compensation)
__device__ volatile unsigned g_gen;
__device__ unsigned g_cnt;

// ---------------- packed f32x2 helpers ----------------
__device__ __forceinline__ u64 add2(u64 a, u64 b) {
    u64 d; asm("add.rn.f32x2 %0,%1,%2;" : "=l"(d) : "l"(a), "l"(b)); return d;
}
__device__ __forceinline__ u64 fma2v(u64 a, u64 b, u64 c) {
    u64 d; asm("fma.rn.f32x2 %0,%1,%2,%3;" : "=l"(d) : "l"(a), "l"(b), "l"(c)); return d;
}
__device__ __forceinline__ u64 dup2(float a) {
    u64 d; asm("mov.b64 %0,{%1,%1};" : "=l"(d) : "f"(a)); return d;
}
#define KM1 0xBF800000BF800000ull   /* packed (-1.0f, -1.0f) */

// Chunk-4 Kahan-FMA (r10-proven numerics): four products into the Kahan y-term.
// 7 FMA-pipe ops per 4 k-steps per packed accumulator pair.
__device__ __forceinline__ void kquad2(u64 &S, u64 &NC,
                                       u64 a0, u64 w0, u64 a1, u64 w1,
                                       u64 a2, u64 w2, u64 a3, u64 w3) {
    u64 p = fma2v(a0, w0, NC);
    p     = fma2v(a1, w1, p);
    p     = fma2v(a2, w2, p);
    u64 y = fma2v(a3, w3, p);
    u64 t = add2(S, y);
    u64 z = fma2v(S, KM1, t);    // t - S
    NC = fma2v(z, KM1, y);       // y - z (= -c_new)
    S = t;
}

// ---------------- grid barrier (graph-replay safe: monotonic gen) -----------
__device__ __forceinline__ void grid_sync(unsigned nblocks) {
    __syncthreads();
    if (threadIdx.x == 0) {
        unsigned g = g_gen;
        __threadfence();
        if (atomicAdd(&g_cnt, 1u) == nblocks - 1u) {
            g_cnt = 0;
            __threadfence();
            g_gen = g + 1u;
        } else {
            while (g_gen == g) { }
        }
        __threadfence();
    }
    __syncthreads();
}

// ---------------- prep: features + init c2 (bit-exact elementwise) ----------
__global__ void prep_kernel(const float* __restrict__ xx,
                            const float* __restrict__ emb1,
                            const float* __restrict__ emb2,
                            const float* __restrict__ emb3,
                            const float* __restrict__ mean,
                            const float* __restrict__ stdv,
                            const float* __restrict__ vmin,
                            const float* __restrict__ vmax) {
    int idx = blockIdx.x*blockDim.x + threadIdx.x;
    if (idx >= B*NP) return;
    int b = idx / NP, p = idx % NP;
    const float* row = xx + (size_t)(b*NP + p)*F_IN;
    float* orow = d_xfeat + (size_t)(b*NP + p)*FC;
    int i1 = (int)fabsf(row[0]);
    int i2 = (int)fabsf(row[1]);
    int i3 = (int)fabsf(row[2]);
    orow[0] = emb1[i1*2+0]; orow[1] = emb1[i1*2+1];
    orow[2] = emb2[i2*2+0]; orow[3] = emb2[i2*2+1];
    orow[4] = emb3[i3*2+0]; orow[5] = emb3[i3*2+1];
    for (int f = 2; f < F_IN; f++) {
        float v = row[f];
        if (f >= 3) {
            float y = __fdiv_rn(__fsub_rn(v, mean[f]), stdv[f]);
            y = fminf(fmaxf(y, -5.0f), 5.0f);
            float sc = __fdiv_rn(2.0f, __fsub_rn(vmax[f], vmin[f]));
            float y2 = __fsub_rn(__fmul_rn(sc, __fsub_rn(y, vmin[f])), 1.0f);
            y2 = fminf(fmaxf(y2, -1.0f), 1.0f);
            v = y2;
        }
        orow[6 + (f - 2)] = v;
    }
    if (p == 0) {
        d_c2[b*2+0] = orow[12];   // ETA_C
        d_c2[b*2+1] = orow[13];   // PHI_C
    }
}

// ---------------- knn: c2 exact (lane TwoProd+Kahan, double merge) ----------
__global__ void knn_kernel(const float* __restrict__ Wc,
                           const float* __restrict__ bc,
                           int compute_c2) {
    int b = blockIdx.x;
    int tid = threadIdx.x;   // 128 threads
    __shared__ float s_ref[2];
    __shared__ float s_d[NP];
    __shared__ int   s_idx[KNN];

    if (compute_c2) {
        int w = tid >> 5, lane = tid & 31;
        if (w < 2) {
            const float* hrow = d_hA + (size_t)b*H;
            int st = lane * 113;
            int en = st + 113; if (en > H) en = H;
            float s = 0.f, c = 0.f;
            for (int k = st; k < en; k++) {
                float a = hrow[k], ww = Wc[k*2+w];
                float p  = __fmul_rn(a, ww);
                float ep = __fmaf_rn(a, ww, -p);
                float y  = __fsub_rn(p, c);
                float t  = __fadd_rn(s, y);
                c = __fsub_rn(__fsub_rn(t, s), y);
                c = __fsub_rn(c, ep);
                s = t;
            }
            double acc = 0.0;
            #pragma unroll
            for (int src = 0; src < 32; src++) {
                float si = __shfl_sync(0xffffffffu, s, src);
                float ci = __shfl_sync(0xffffffffu, c, src);
                acc += (double)si - (double)ci;
            }
            if (lane == 0)
                s_ref[w] = __fadd_rn((float)acc, bc[w]);
        }
    } else {
        if (tid < 2) s_ref[tid] = d_c2[b*2+tid];
    }
    __syncthreads();

    if (tid < NP) {
        float dx = __fsub_rn(d_xfeat[(size_t)(b*NP + tid)*FC + 12], s_ref[0]);
        float dy = __fsub_rn(d_xfeat[(size_t)(b*NP + tid)*FC + 13], s_ref[1]);
        s_d[tid] = __fsqrt_rn(__fadd_rn(__fmul_rn(dx,dx), __fmul_rn(dy,dy)));
    }
    __syncthreads();
    if (tid < NP) {
        float mine = s_d[tid];
        int rank = 0;
        #pragma unroll 4
        for (int j = 0; j < NP; j++) {
            float dj = s_d[j];
            rank += (dj < mine) || (dj == mine && j < tid);  // stable tie-break
        }
        if (rank < KNN) s_idx[rank] = tid;
    }
    __syncthreads();
    for (int i = tid; i < GDIM; i += 128) {
        int k = i / FC, f = i - k*FC;
        d_g[(size_t)b*GDIM + i] = d_xfeat[(size_t)(b*NP + s_idx[k])*FC + f];
    }
}

// ---------------- fused layer: row-packed 2x4 tile, dup-W SMEM, chunk-4 -----
// grid (57, 10), 256 thr. Thread: rows {2*m16, 2*m16+1} x cols [n16*4, +4).
// Accumulator lanes = (row0,row1); a-operand = sA2 row-pair directly (no MOVs);
// w-operand read pre-duplicated from sWd.
__global__ void __launch_bounds__(256, 4)
layer_kernel(const float* __restrict__ A, int Kd,
             const float* __restrict__ W,
             const float* __restrict__ bias,
             const float* __restrict__ gamma,
             const float* __restrict__ beta,
             const float* __restrict__ mmean,
             const float* __restrict__ mvar,
             float* __restrict__ out) {
    __shared__ __align__(16) float2 sA2[TILEK][17];    // [k][m16]=(row2m,row2m+1)
    __shared__ __align__(16) u64    sWd[TILEK][NCOLS]; // [k][col] = (w,w)
    int tid  = threadIdx.x;
    int lane = tid & 31;
    int m16  = lane & 15;                       // row pair index
    int n16  = ((tid >> 5) << 1) | (lane >> 4); // 0..15, 4 cols each
    int n0   = blockIdx.x * NCOLS;
    int kb   = blockIdx.y;
    int cloc = n16 * 4;
    int c0   = n0 + cloc;

    int Kc = ((Kd + SPLITK - 1)/SPLITK + 7) & ~7;
    int kstart = kb * Kc;
    int kend   = kstart + Kc; if (kend > Kd) kend = Kd;

    u64 S0=0,N0=0, S1=0,N1=0, S2=0,N2=0, S3=0,N3=0;

    int am = tid >> 3;            // A row 0..31
    int aq = (tid & 7) << 2;      // A k-offset (float4)
    int wk = tid >> 3;            // W k-row 0..31
    int wq = (tid & 7) << 3;      // W col offset (8 cols/thread)

    int k0 = kstart;
    int klen = kend - k0; if (klen > TILEK) klen = TILEK;   // mult of 8
    // prefetch tile 0
    float4 pa  = make_float4(0.f,0.f,0.f,0.f);
    float4 pw0 = make_float4(0.f,0.f,0.f,0.f);
    float4 pw1 = make_float4(0.f,0.f,0.f,0.f);
    if (aq < klen)
        pa = *reinterpret_cast<const float4*>(A + (size_t)am*Kd + k0 + aq);
    if (wk < klen) {
        int nn = n0 + wq;
        if (nn < H)
            pw0 = *reinterpret_cast<const float4*>(W + (size_t)(k0+wk)*H + nn);
        if (nn + 4 < H)
            pw1 = *reinterpret_cast<const float4*>(W + (size_t)(k0+wk)*H + nn + 4);
    }

    for (;;) {
        __syncthreads();           // previous compute done; smem free
        if (aq < klen) {
            int mh = am >> 1, ml = am & 1;
            reinterpret_cast<float*>(&sA2[aq+0][mh])[ml] = pa.x;
            reinterpret_cast<float*>(&sA2[aq+1][mh])[ml] = pa.y;
            reinterpret_cast<float*>(&sA2[aq+2][mh])[ml] = pa.z;
            reinterpret_cast<float*>(&sA2[aq+3][mh])[ml] = pa.w;
        }
        if (wk < klen) {
            ulonglong2 v;
            v.x = dup2(pw0.x); v.y = dup2(pw0.y);
            *reinterpret_cast<ulonglong2*>(&sWd[wk][wq])     = v;
            v.x = dup2(pw0.z); v.y = dup2(pw0.w);
            *reinterpret_cast<ulonglong2*>(&sWd[wk][wq + 2]) = v;
            v.x = dup2(pw1.x); v.y = dup2(pw1.y);
            *reinterpret_cast<ulonglong2*>(&sWd[wk][wq + 4]) = v;
            v.x = dup2(pw1.z); v.y = dup2(pw1.w);
            *reinterpret_cast<ulonglong2*>(&sWd[wk][wq + 6]) = v;
        }

        int nk0 = k0 + TILEK;
        bool more = nk0 < kend;
        int nklen = kend - nk0; if (nklen > TILEK) nklen = TILEK;
        if (more) {   // issue next tile's LDGs before compute (latency overlap)
            pa  = make_float4(0.f,0.f,0.f,0.f);
            pw0 = make_float4(0.f,0.f,0.f,0.f);
            pw1 = make_float4(0.f,0.f,0.f,0.f);
            if (aq < nklen)
                pa = *reinterpret_cast<const float4*>(A + (size_t)am*Kd + nk0 + aq);
            if (wk < nklen) {
                int nn = n0 + wq;
                if (nn < H)
                    pw0 = *reinterpret_cast<const float4*>(W + (size_t)(nk0+wk)*H + nn);
                if (nn + 4 < H)
                    pw1 = *reinterpret_cast<const float4*>(W + (size_t)(nk0+wk)*H + nn + 4);
            }
        }
        __syncthreads();           // smem tile ready

        if (klen == TILEK) {
            #pragma unroll
            for (int kk = 0; kk < TILEK; kk += 4) {
                u64 A0 = *reinterpret_cast<const u64*>(&sA2[kk+0][m16]);
                u64 A1 = *reinterpret_cast<const u64*>(&sA2[kk+1][m16]);
                u64 A2 = *reinterpret_cast<const u64*>(&sA2[kk+2][m16]);
                u64 A3 = *reinterpret_cast<const u64*>(&sA2[kk+3][m16]);
                ulonglong2 w0a = *reinterpret_cast<const ulonglong2*>(&sWd[kk+0][cloc]);
                ulonglong2 w1a = *reinterpret_cast<const ulonglong2*>(&sWd[kk+1][cloc]);
                ulonglong2 w2a = *reinterpret_cast<const ulonglong2*>(&sWd[kk+2][cloc]);
                ulonglong2 w3a = *reinterpret_cast<const ulonglong2*>(&sWd[kk+3][cloc]);
                kquad2(S0,N0, A0,w0a.x, A1,w1a.x, A2,w2a.x, A3,w3a.x);
                kquad2(S1,N1, A0,w0a.y, A1,w1a.y, A2,w2a.y, A3,w3a.y);
                ulonglong2 w0b = *reinterpret_cast<const ulonglong2*>(&sWd[kk+0][cloc+2]);
                ulonglong2 w1b = *reinterpret_cast<const ulonglong2*>(&sWd[kk+1][cloc+2]);
                ulonglong2 w2b = *reinterpret_cast<const ulonglong2*>(&sWd[kk+2][cloc+2]);
                ulonglong2 w3b = *reinterpret_cast<const ulonglong2*>(&sWd[kk+3][cloc+2]);
                kquad2(S2,N2, A0,w0b.x, A1,w1b.x, A2,w2b.x, A3,w3b.x);
                kquad2(S3,N3, A0,w0b.y, A1,w1b.y, A2,w2b.y, A3,w3b.y);
            }
        } else {
            for (int kk = 0; kk < klen; kk += 4) {
                u64 A0 = *reinterpret_cast<const u64*>(&sA2[kk+0][m16]);
                u64 A1 = *reinterpret_cast<const u64*>(&sA2[kk+1][m16]);
                u64 A2 = *reinterpret_cast<const u64*>(&sA2[kk+2][m16]);
                u64 A3 = *reinterpret_cast<const u64*>(&sA2[kk+3][m16]);
                ulonglong2 w0a = *reinterpret_cast<const ulonglong2*>(&sWd[kk+0][cloc]);
                ulonglong2 w1a = *reinterpret_cast<const ulonglong2*>(&sWd[kk+1][cloc]);
                ulonglong2 w2a = *reinterpret_cast<const ulonglong2*>(&sWd[kk+2][cloc]);
                ulonglong2 w3a = *reinterpret_cast<const ulonglong2*>(&sWd[kk+3][cloc]);
                kquad2(S0,N0, A0,w0a.x, A1,w1a.x, A2,w2a.x, A3,w3a.x);
                kquad2(S1,N1, A0,w0a.y, A1,w1a.y, A2,w2a.y, A3,w3a.y);
                ulonglong2 w0b = *reinterpret_cast<const ulonglong2*>(&sWd[kk+0][cloc+2]);
                ulonglong2 w1b = *reinterpret_cast<const ulonglong2*>(&sWd[kk+1][cloc+2]);
                ulonglong2 w2b = *reinterpret_cast<const ulonglong2*>(&sWd[kk+2][cloc+2]);
                ulonglong2 w3b = *reinterpret_cast<const ulonglong2*>(&sWd[kk+3][cloc+2]);
                kquad2(S2,N2, A0,w0b.x, A1,w1b.x, A2,w2b.x, A3,w3b.x);
                kquad2(S3,N3, A0,w0b.y, A1,w1b.y, A2,w2b.y, A3,w3b.y);
            }
        }
        if (!more) break;
        k0 = nk0; klen = nklen;
    }

    if (c0 < H) {   // c0..c0+3 all valid (c0 mult of 4, H mult of 4)
        size_t i0 = ((size_t)(kb*16 + m16))*H + c0;   // u64 index, 16B aligned
        ulonglong2 v;
        v.x = S0; v.y = S1; *reinterpret_cast<ulonglong2*>(&d_pS[i0])   = v;
        v.x = S2; v.y = S3; *reinterpret_cast<ulonglong2*>(&d_pS[i0+2]) = v;
        v.x = N0; v.y = N1; *reinterpret_cast<ulonglong2*>(&d_pC[i0])   = v;
        v.x = N2; v.y = N3; *reinterpret_cast<ulonglong2*>(&d_pC[i0+2]) = v;
    }

    grid_sync(gridDim.x * gridDim.y);

    // phase 2: double-precision combine (exact) + bias + BN + ReLU
    int nthr = gridDim.x * gridDim.y * 256;
    int bid  = blockIdx.y * gridDim.x + blockIdx.x;
    for (int gi = bid*256 + tid; gi < B*H; gi += nthr) {
        int n   = gi % H;
        int row = gi / H;
        int rp = row >> 1, sub = row & 1;
        double acc = 0.0;
        #pragma unroll
        for (int k = 0; k < SPLITK; k++) {
            size_t off = ((size_t)(k*16 + rp))*H + n;
            acc += (double)reinterpret_cast<const float*>(&d_pS[off])[sub];
            acc += (double)reinterpret_cast<const float*>(&d_pC[off])[sub];  // NC negated
        }
        float h = __fadd_rn((float)acc, bias[n]);
        float r = __fdiv_rn(1.0f, __fsqrt_rn(__fadd_rn(mvar[n], EPSB)));
        float o = __fadd_rn(__fmul_rn(__fmul_rn(gamma[n], __fsub_rn(h, mmean[n])), r), beta[n]);
        out[gi] = fmaxf(o, 0.f);
    }
}

// ---------------- heads ------------------------------------------------------
__global__ void heads_kernel(const float* __restrict__ xx,
                             const float* __restrict__ W2,
                             const float* __restrict__ b2,
                             const float* __restrict__ W100,
                             const float* __restrict__ b100,
                             float* __restrict__ out) {
    int b = blockIdx.x, tid = threadIdx.x;   // 256 threads
    __shared__ float sh[H];
    __shared__ float s_logit[NP];
    __shared__ float s_x2[2];
    for (int nn = tid; nn < H; nn += 256) sh[nn] = d_hA[(size_t)b*H + nn];
    __syncthreads();
    if (tid < NP) {
        float acc = 0.f;
        for (int nn = 0; nn < H; nn++)
            acc = __fmaf_rn(sh[nn], W100[(size_t)nn*NP + tid], acc);
        s_logit[tid] = __fadd_rn(acc, b100[tid]);
    } else if (tid < NP + 2) {
        int j = tid - NP;
        float acc = 0.f;
        for (int nn = 0; nn < H; nn++)
            acc = __fmaf_rn(sh[nn], W2[nn*2 + j], acc);
        s_x2[j] = __fadd_rn(acc, b2[j]);
    }
    __syncthreads();
    if (tid == 0) {
        float mx = s_logit[0];
        for (int i = 1; i < NP; i++) mx = fmaxf(mx, s_logit[i]);
        float sum = 0.f;
        for (int i = 0; i < NP; i++) { float ev = expf(__fsub_rn(s_logit[i], mx)); s_logit[i] = ev; sum += ev; }
        const float* xb = xx + (size_t)b*NP*F_IN;
        float px = 0.f, py = 0.f, pz = 0.f, E = 0.f;
        for (int i = 0; i < NP; i++) {
            float w = __fmul_rn(__fdiv_rn(s_logit[i], sum), xb[i*F_IN + 7]);
            px = __fmaf_rn(xb[i*F_IN + 3], w, px);
            py = __fmaf_rn(xb[i*F_IN + 4], w, py);
            pz = __fmaf_rn(xb[i*F_IN + 5], w, pz);
            E  = __fmaf_rn(xb[i*F_IN + 6], w, E);
        }
        float px2 = __fmul_rn(px,px), py2 = __fmul_rn(py,py), pz2 = __fmul_rn(pz,pz);
        float pt = __fsqrt_rn(__fadd_rn(px2, py2));
        float mass2 = __fsub_rn(__fsub_rn(__fsub_rn(__fmul_rn(E,E), px2), py2), pz2);
        float absp = __fsqrt_rn(__fadd_rn(__fadd_rn(px2, py2), pz2));
        float denom = (absp == 0.f) ? 1.f : absp;
        float cosT  = (absp == 0.f) ? 1.f : __fdiv_rn(pz, denom);
        bool ok = (__fmul_rn(cosT,cosT) < 1.f);
        float ratio = ok ? __fdiv_rn(__fsub_rn(1.f, cosT), __fadd_rn(1.f, cosT)) : 1.f;
        float eta = ok ? __fmul_rn(-0.5f, logf(ratio)) : 0.f;
        float phi = (px == 0.f && py == 0.f) ? 0.f : atan2f(py, px);
        out[b*6+0] = s_x2[0];
        out[b*6+1] = s_x2[1];
        out[b*6+2] = pt;
        out[b*6+3] = eta;
        out[b*6+4] = phi;
        out[b*6+5] = mass2;
    }
}

// ---------------- launch ----------------
extern "C" void kernel_launch(void* const* d_in, const int* in_sizes, int n_in,
                              void* d_out, int out_size) {
    const float* xx    = (const float*)d_in[0];
    const float* emb1  = (const float*)d_in[1];
    const float* emb2  = (const float*)d_in[2];
    const float* emb3  = (const float*)d_in[3];
    const float* mean  = (const float*)d_in[4];
    const float* stdv  = (const float*)d_in[5];
    const float* vmin  = (const float*)d_in[6];
    const float* vmax  = (const float*)d_in[7];
    const float* W0    = (const float*)d_in[8];
    const float* b0    = (const float*)d_in[9];
    const float* Wh    = (const float*)d_in[10];
    const float* bh    = (const float*)d_in[11];
    const float* gamma = (const float*)d_in[12];
    const float* beta  = (const float*)d_in[13];
    const float* mmean = (const float*)d_in[14];
    const float* mvar  = (const float*)d_in[15];
    const float* Wc    = (const float*)d_in[16];
    const float* bc    = (const float*)d_in[17];
    const float* W2    = (const float*)d_in[18];
    const float* b2    = (const float*)d_in[19];
    const float* W100  = (const float*)d_in[20];
    const float* b100  = (const float*)d_in[21];

    float *pG, *pA, *pB;
    cudaGetSymbolAddress((void**)&pG, d_g);
    cudaGetSymbolAddress((void**)&pA, d_hA);
    cudaGetSymbolAddress((void**)&pB, d_hB);

    prep_kernel<<<(B*NP + 255)/256, 256>>>(xx, emb1, emb2, emb3, mean, stdv, vmin, vmax);

    const dim3 GL(NBX, SPLITK);   // (57, 10) = 570 blocks <= 592 co-resident

    for (int it = 0; it < NP; it++) {
        knn_kernel<<<B, 128>>>(Wc, bc, it > 0 ? 1 : 0);

        layer_kernel<<<GL, 256>>>(pG, GDIM, W0, b0,
                                  gamma, beta, mmean, mvar, pA);
        layer_kernel<<<GL, 256>>>(pA, H, Wh + 0*(size_t)H*H, bh + 0*H,
                                  gamma + 1*H, beta + 1*H, mmean + 1*H, mvar + 1*H, pB);
        layer_kernel<<<GL, 256>>>(pB, H, Wh + 1*(size_t)H*H, bh + 1*H,
                                  gamma + 2*H, beta + 2*H, mmean + 2*H, mvar + 2*H, pA);
        layer_kernel<<<GL, 256>>>(pA, H, Wh + 2*(size_t)H*H, bh + 2*H,
                                  gamma + 3*H, beta + 3*H, mmean + 3*H, mvar + 3*H, pB);
        layer_kernel<<<GL, 256>>>(pB, H, Wh + 3*(size_t)H*H, bh + 3*H,
                                  gamma + 4*H, beta + 4*H, mmean + 4*H, mvar + 4*H, pA);
    }

    heads_kernel<<<B, 256>>>(xx, W2, b2, W100, b100, (float*)d_out);
}

// round 15
// speedup vs baseline: 1.2372x; 1.2372x over previous
#include <cuda_runtime.h>
#include <math.h>

#define B    32
#define NP   100
#define F_IN 36
#define FC   40
#define KNN  11
#define GDIM 440
#define H    3600
#define NLAY 5
#define EPSB 0.001f
#define SPLITK 10
#define TILEK  32
#define NCOLS  64
#define NBX    57

typedef unsigned long long u64;

// ---------------- device scratch ----------------
__device__ float d_xfeat[B*NP*FC];
__device__ float d_g[B*GDIM];
__device__ float d_hA[B*H];
__device__ float d_hB[B*H];
__device__ float d_c2[B*2];
__device__ float d_partS[SPLITK*B*H];
__device__ float d_partC[SPLITK*B*H];   // NC (negated compensation)
__device__ volatile unsigned g_gen;
__device__ unsigned g_cnt;

// ---------------- packed f32x2 helpers ----------------
__device__ __forceinline__ u64 add2(u64 a, u64 b) {
    u64 d; asm("add.rn.f32x2 %0,%1,%2;" : "=l"(d) : "l"(a), "l"(b)); return d;
}
__device__ __forceinline__ u64 fma2v(u64 a, u64 b, u64 c) {
    u64 d; asm("fma.rn.f32x2 %0,%1,%2,%3;" : "=l"(d) : "l"(a), "l"(b), "l"(c)); return d;
}
__device__ __forceinline__ u64 dup2(float a) {
    u64 d; asm("mov.b64 %0,{%1,%1};" : "=l"(d) : "f"(a)); return d;
}
__device__ __forceinline__ void unpack2(u64 v, float &lo, float &hi) {
    asm("mov.b64 {%0,%1}, %2;" : "=f"(lo), "=f"(hi) : "l"(v));
}
#define KM1 0xBF800000BF800000ull   /* packed (-1.0f, -1.0f) */

// Chunk-4 Kahan-FMA (r10/r14-proven numerics): four products into the y-term.
// 7 FMA-pipe ops per 4 k-steps per packed accumulator.
__device__ __forceinline__ void kquad2(u64 &S, u64 &NC,
                                       u64 a0, u64 w0, u64 a1, u64 w1,
                                       u64 a2, u64 w2, u64 a3, u64 w3) {
    u64 p = fma2v(a0, w0, NC);
    p     = fma2v(a1, w1, p);
    p     = fma2v(a2, w2, p);
    u64 y = fma2v(a3, w3, p);
    u64 t = add2(S, y);
    u64 z = fma2v(S, KM1, t);    // t - S
    NC = fma2v(z, KM1, y);       // y - z (= -c_new)
    S = t;
}

// ---------------- grid barrier (graph-replay safe: monotonic gen) -----------
__device__ __forceinline__ void grid_sync(unsigned nblocks) {
    __syncthreads();
    if (threadIdx.x == 0) {
        unsigned g = g_gen;
        __threadfence();
        if (atomicAdd(&g_cnt, 1u) == nblocks - 1u) {
            g_cnt = 0;
            __threadfence();
            g_gen = g + 1u;
        } else {
            while (g_gen == g) { }
        }
        __threadfence();
    }
    __syncthreads();
}

// ---------------- prep: features + init c2 (bit-exact elementwise) ----------
__global__ void prep_kernel(const float* __restrict__ xx,
                            const float* __restrict__ emb1,
                            const float* __restrict__ emb2,
                            const float* __restrict__ emb3,
                            const float* __restrict__ mean,
                            const float* __restrict__ stdv,
                            const float* __restrict__ vmin,
                            const float* __restrict__ vmax) {
    int idx = blockIdx.x*blockDim.x + threadIdx.x;
    if (idx >= B*NP) return;
    int b = idx / NP, p = idx % NP;
    const float* row = xx + (size_t)(b*NP + p)*F_IN;
    float* orow = d_xfeat + (size_t)(b*NP + p)*FC;
    int i1 = (int)fabsf(row[0]);
    int i2 = (int)fabsf(row[1]);
    int i3 = (int)fabsf(row[2]);
    orow[0] = emb1[i1*2+0]; orow[1] = emb1[i1*2+1];
    orow[2] = emb2[i2*2+0]; orow[3] = emb2[i2*2+1];
    orow[4] = emb3[i3*2+0]; orow[5] = emb3[i3*2+1];
    for (int f = 2; f < F_IN; f++) {
        float v = row[f];
        if (f >= 3) {
            float y = __fdiv_rn(__fsub_rn(v, mean[f]), stdv[f]);
            y = fminf(fmaxf(y, -5.0f), 5.0f);
            float sc = __fdiv_rn(2.0f, __fsub_rn(vmax[f], vmin[f]));
            float y2 = __fsub_rn(__fmul_rn(sc, __fsub_rn(y, vmin[f])), 1.0f);
            y2 = fminf(fmaxf(y2, -1.0f), 1.0f);
            v = y2;
        }
        orow[6 + (f - 2)] = v;
    }
    if (p == 0) {
        d_c2[b*2+0] = orow[12];   // ETA_C
        d_c2[b*2+1] = orow[13];   // PHI_C
    }
}

// ---------------- knn: c2 exact (lane TwoProd+Kahan, double merge) ----------
__global__ void knn_kernel(const float* __restrict__ Wc,
                           const float* __restrict__ bc,
                           int compute_c2) {
    int b = blockIdx.x;
    int tid = threadIdx.x;   // 128 threads
    __shared__ float s_ref[2];
    __shared__ float s_d[NP];
    __shared__ int   s_idx[KNN];

    if (compute_c2) {
        int w = tid >> 5, lane = tid & 31;
        if (w < 2) {
            const float* hrow = d_hA + (size_t)b*H;
            int st = lane * 113;
            int en = st + 113; if (en > H) en = H;
            float s = 0.f, c = 0.f;
            for (int k = st; k < en; k++) {
                float a = hrow[k], ww = Wc[k*2+w];
                float p  = __fmul_rn(a, ww);
                float ep = __fmaf_rn(a, ww, -p);
                float y  = __fsub_rn(p, c);
                float t  = __fadd_rn(s, y);
                c = __fsub_rn(__fsub_rn(t, s), y);
                c = __fsub_rn(c, ep);
                s = t;
            }
            double acc = 0.0;
            #pragma unroll
            for (int src = 0; src < 32; src++) {
                float si = __shfl_sync(0xffffffffu, s, src);
                float ci = __shfl_sync(0xffffffffu, c, src);
                acc += (double)si - (double)ci;
            }
            if (lane == 0)
                s_ref[w] = __fadd_rn((float)acc, bc[w]);
        }
    } else {
        if (tid < 2) s_ref[tid] = d_c2[b*2+tid];
    }
    __syncthreads();

    if (tid < NP) {
        float dx = __fsub_rn(d_xfeat[(size_t)(b*NP + tid)*FC + 12], s_ref[0]);
        float dy = __fsub_rn(d_xfeat[(size_t)(b*NP + tid)*FC + 13], s_ref[1]);
        s_d[tid] = __fsqrt_rn(__fadd_rn(__fmul_rn(dx,dx), __fmul_rn(dy,dy)));
    }
    __syncthreads();
    if (tid < NP) {
        float mine = s_d[tid];
        int rank = 0;
        #pragma unroll 4
        for (int j = 0; j < NP; j++) {
            float dj = s_d[j];
            rank += (dj < mine) || (dj == mine && j < tid);  // stable tie-break
        }
        if (rank < KNN) s_idx[rank] = tid;
    }
    __syncthreads();
    for (int i = tid; i < GDIM; i += 128) {
        int k = i / FC, f = i - k*FC;
        d_g[(size_t)b*GDIM + i] = d_xfeat[(size_t)(b*NP + s_idx[k])*FC + f];
    }
}

// ---------------- fused layer: 2x4 tile, double-buffered, chunk-4 Kahan -----
// grid (57, 10), 256 thr. Thread: rows {2*m16, 2*m16+1} x cols [n16*4, +4).
// SMEM layout = r13 (row-pair A, plain W); dup in registers. 1 barrier/tile.
__global__ void __launch_bounds__(256, 4)
layer_kernel(const float* __restrict__ A, int Kd,
             const float* __restrict__ W,
             const float* __restrict__ bias,
             const float* __restrict__ gamma,
             const float* __restrict__ beta,
             const float* __restrict__ mmean,
             const float* __restrict__ mvar,
             float* __restrict__ out) {
    __shared__ __align__(16) float2 sA2[2][TILEK][17];   // [buf][k][m16]
    __shared__ __align__(16) float  sW[2][TILEK][NCOLS]; // [buf][k][col]
    int tid  = threadIdx.x;
    int lane = tid & 31;
    int m16  = lane & 15;                       // row pair index
    int n16  = ((tid >> 5) << 1) | (lane >> 4); // 0..15, 4 cols each
    int n0   = blockIdx.x * NCOLS;
    int kb   = blockIdx.y;
    int cloc = n16 * 4;
    int c0   = n0 + cloc;

    int Kc = ((Kd + SPLITK - 1)/SPLITK + 7) & ~7;
    int kstart = kb * Kc;
    int kend   = kstart + Kc; if (kend > Kd) kend = Kd;

    u64 S00=0,N00=0, S01=0,N01=0, S10=0,N10=0, S11=0,N11=0;

    int am = tid >> 3;            // A row 0..31
    int aq = (tid & 7) << 2;      // A k-offset (float4)
    int wk = tid >> 3;            // W k-row 0..31
    int wq = (tid & 7) << 3;      // W col offset (two float4)
    int mh = am >> 1, ml = am & 1;

    int k0 = kstart;
    int klen = kend - k0; if (klen > TILEK) klen = TILEK;   // mult of 8
    // prefetch + stage tile 0 into buf 0
    {
        float4 pa  = make_float4(0.f,0.f,0.f,0.f);
        float4 pw0 = make_float4(0.f,0.f,0.f,0.f);
        float4 pw1 = make_float4(0.f,0.f,0.f,0.f);
        if (aq < klen)
            pa = *reinterpret_cast<const float4*>(A + (size_t)am*Kd + k0 + aq);
        if (wk < klen) {
            int nn = n0 + wq;
            if (nn < H)
                pw0 = *reinterpret_cast<const float4*>(W + (size_t)(k0+wk)*H + nn);
            if (nn + 4 < H)
                pw1 = *reinterpret_cast<const float4*>(W + (size_t)(k0+wk)*H + nn + 4);
        }
        if (aq < klen) {
            reinterpret_cast<float*>(&sA2[0][aq+0][mh])[ml] = pa.x;
            reinterpret_cast<float*>(&sA2[0][aq+1][mh])[ml] = pa.y;
            reinterpret_cast<float*>(&sA2[0][aq+2][mh])[ml] = pa.z;
            reinterpret_cast<float*>(&sA2[0][aq+3][mh])[ml] = pa.w;
        }
        if (wk < klen) {
            *reinterpret_cast<float4*>(&sW[0][wk][wq])     = pw0;
            *reinterpret_cast<float4*>(&sW[0][wk][wq + 4]) = pw1;
        }
    }
    __syncthreads();

    int buf = 0;
    for (;;) {
        int nk0 = k0 + TILEK;
        bool more = nk0 < kend;
        int nklen = kend - nk0; if (nklen > TILEK) nklen = TILEK;

        float4 pa  = make_float4(0.f,0.f,0.f,0.f);
        float4 pw0 = make_float4(0.f,0.f,0.f,0.f);
        float4 pw1 = make_float4(0.f,0.f,0.f,0.f);
        if (more) {   // LDG next tile before compute (latency overlap)
            if (aq < nklen)
                pa = *reinterpret_cast<const float4*>(A + (size_t)am*Kd + nk0 + aq);
            if (wk < nklen) {
                int nn = n0 + wq;
                if (nn < H)
                    pw0 = *reinterpret_cast<const float4*>(W + (size_t)(nk0+wk)*H + nn);
                if (nn + 4 < H)
                    pw1 = *reinterpret_cast<const float4*>(W + (size_t)(nk0+wk)*H + nn + 4);
            }
        }

        // compute current tile from buf
        if (klen == TILEK) {
            #pragma unroll
            for (int kk = 0; kk < TILEK; kk += 4) {
                u64 A0 = *reinterpret_cast<const u64*>(&sA2[buf][kk+0][m16]);
                u64 A1 = *reinterpret_cast<const u64*>(&sA2[buf][kk+1][m16]);
                u64 A2 = *reinterpret_cast<const u64*>(&sA2[buf][kk+2][m16]);
                u64 A3 = *reinterpret_cast<const u64*>(&sA2[buf][kk+3][m16]);
                float a00,a01,a10,a11,a20,a21,a30,a31;
                unpack2(A0, a00, a01);
                unpack2(A1, a10, a11);
                unpack2(A2, a20, a21);
                unpack2(A3, a30, a31);
                u64 d00 = dup2(a00), d01 = dup2(a01);
                u64 d10 = dup2(a10), d11 = dup2(a11);
                u64 d20 = dup2(a20), d21 = dup2(a21);
                u64 d30 = dup2(a30), d31 = dup2(a31);
                ulonglong2 w0 = *reinterpret_cast<const ulonglong2*>(&sW[buf][kk+0][cloc]);
                ulonglong2 w1 = *reinterpret_cast<const ulonglong2*>(&sW[buf][kk+1][cloc]);
                ulonglong2 w2 = *reinterpret_cast<const ulonglong2*>(&sW[buf][kk+2][cloc]);
                ulonglong2 w3 = *reinterpret_cast<const ulonglong2*>(&sW[buf][kk+3][cloc]);
                kquad2(S00,N00, d00,w0.x, d10,w1.x, d20,w2.x, d30,w3.x);
                kquad2(S01,N01, d00,w0.y, d10,w1.y, d20,w2.y, d30,w3.y);
                kquad2(S10,N10, d01,w0.x, d11,w1.x, d21,w2.x, d31,w3.x);
                kquad2(S11,N11, d01,w0.y, d11,w1.y, d21,w2.y, d31,w3.y);
            }
        } else {
            for (int kk = 0; kk < klen; kk += 4) {
                u64 A0 = *reinterpret_cast<const u64*>(&sA2[buf][kk+0][m16]);
                u64 A1 = *reinterpret_cast<const u64*>(&sA2[buf][kk+1][m16]);
                u64 A2 = *reinterpret_cast<const u64*>(&sA2[buf][kk+2][m16]);
                u64 A3 = *reinterpret_cast<const u64*>(&sA2[buf][kk+3][m16]);
                float a00,a01,a10,a11,a20,a21,a30,a31;
                unpack2(A0, a00, a01);
                unpack2(A1, a10, a11);
                unpack2(A2, a20, a21);
                unpack2(A3, a30, a31);
                u64 d00 = dup2(a00), d01 = dup2(a01);
                u64 d10 = dup2(a10), d11 = dup2(a11);
                u64 d20 = dup2(a20), d21 = dup2(a21);
                u64 d30 = dup2(a30), d31 = dup2(a31);
                ulonglong2 w0 = *reinterpret_cast<const ulonglong2*>(&sW[buf][kk+0][cloc]);
                ulonglong2 w1 = *reinterpret_cast<const ulonglong2*>(&sW[buf][kk+1][cloc]);
                ulonglong2 w2 = *reinterpret_cast<const ulonglong2*>(&sW[buf][kk+2][cloc]);
                ulonglong2 w3 = *reinterpret_cast<const ulonglong2*>(&sW[buf][kk+3][cloc]);
                kquad2(S00,N00, d00,w0.x, d10,w1.x, d20,w2.x, d30,w3.x);
                kquad2(S01,N01, d00,w0.y, d10,w1.y, d20,w2.y, d30,w3.y);
                kquad2(S10,N10, d01,w0.x, d11,w1.x, d21,w2.x, d31,w3.x);
                kquad2(S11,N11, d01,w0.y, d11,w1.y, d21,w2.y, d31,w3.y);
            }
        }
        if (!more) break;

        // stage next tile into the other buffer; single barrier
        int nb = buf ^ 1;
        if (aq < nklen) {
            reinterpret_cast<float*>(&sA2[nb][aq+0][mh])[ml] = pa.x;
            reinterpret_cast<float*>(&sA2[nb][aq+1][mh])[ml] = pa.y;
            reinterpret_cast<float*>(&sA2[nb][aq+2][mh])[ml] = pa.z;
            reinterpret_cast<float*>(&sA2[nb][aq+3][mh])[ml] = pa.w;
        }
        if (wk < nklen) {
            *reinterpret_cast<float4*>(&sW[nb][wk][wq])     = pw0;
            *reinterpret_cast<float4*>(&sW[nb][wk][wq + 4]) = pw1;
        }
        __syncthreads();
        buf = nb;
        k0 = nk0; klen = nklen;
    }

    if (c0 < H) {   // c0..c0+3 all valid (H mult of 4)
        int r0 = 2*m16;
        size_t i0 = ((size_t)kb*B + r0)*H + c0;
        *reinterpret_cast<u64*>(&d_partS[i0])     = S00;
        *reinterpret_cast<u64*>(&d_partC[i0])     = N00;
        *reinterpret_cast<u64*>(&d_partS[i0+2])   = S01;
        *reinterpret_cast<u64*>(&d_partC[i0+2])   = N01;
        size_t i1 = i0 + H;   // row r0+1
        *reinterpret_cast<u64*>(&d_partS[i1])     = S10;
        *reinterpret_cast<u64*>(&d_partC[i1])     = N10;
        *reinterpret_cast<u64*>(&d_partS[i1+2])   = S11;
        *reinterpret_cast<u64*>(&d_partC[i1+2])   = N11;
    }

    grid_sync(gridDim.x * gridDim.y);

    // phase 2: double-precision combine (exact) + bias + BN + ReLU
    int nthr = gridDim.x * gridDim.y * 256;
    int bid  = blockIdx.y * gridDim.x + blockIdx.x;
    for (int gi = bid*256 + tid; gi < B*H; gi += nthr) {
        int n = gi % H;
        double acc = 0.0;
        #pragma unroll
        for (int k = 0; k < SPLITK; k++) {
            acc += (double)d_partS[k*(B*H) + gi];
            acc += (double)d_partC[k*(B*H) + gi];   // NC already negated
        }
        float h = __fadd_rn((float)acc, bias[n]);
        float r = __fdiv_rn(1.0f, __fsqrt_rn(__fadd_rn(mvar[n], EPSB)));
        float o = __fadd_rn(__fmul_rn(__fmul_rn(gamma[n], __fsub_rn(h, mmean[n])), r), beta[n]);
        out[gi] = fmaxf(o, 0.f);
    }
}

// ---------------- heads ------------------------------------------------------
__global__ void heads_kernel(const float* __restrict__ xx,
                             const float* __restrict__ W2,
                             const float* __restrict__ b2,
                             const float* __restrict__ W100,
                             const float* __restrict__ b100,
                             float* __restrict__ out) {
    int b = blockIdx.x, tid = threadIdx.x;   // 256 threads
    __shared__ float sh[H];
    __shared__ float s_logit[NP];
    __shared__ float s_x2[2];
    for (int nn = tid; nn < H; nn += 256) sh[nn] = d_hA[(size_t)b*H + nn];
    __syncthreads();
    if (tid < NP) {
        float acc = 0.f;
        for (int nn = 0; nn < H; nn++)
            acc = __fmaf_rn(sh[nn], W100[(size_t)nn*NP + tid], acc);
        s_logit[tid] = __fadd_rn(acc, b100[tid]);
    } else if (tid < NP + 2) {
        int j = tid - NP;
        float acc = 0.f;
        for (int nn = 0; nn < H; nn++)
            acc = __fmaf_rn(sh[nn], W2[nn*2 + j], acc);
        s_x2[j] = __fadd_rn(acc, b2[j]);
    }
    __syncthreads();
    if (tid == 0) {
        float mx = s_logit[0];
        for (int i = 1; i < NP; i++) mx = fmaxf(mx, s_logit[i]);
        float sum = 0.f;
        for (int i = 0; i < NP; i++) { float ev = expf(__fsub_rn(s_logit[i], mx)); s_logit[i] = ev; sum += ev; }
        const float* xb = xx + (size_t)b*NP*F_IN;
        float px = 0.f, py = 0.f, pz = 0.f, E = 0.f;
        for (int i = 0; i < NP; i++) {
            float w = __fmul_rn(__fdiv_rn(s_logit[i], sum), xb[i*F_IN + 7]);
            px = __fmaf_rn(xb[i*F_IN + 3], w, px);
            py = __fmaf_rn(xb[i*F_IN + 4], w, py);
            pz = __fmaf_rn(xb[i*F_IN + 5], w, pz);
            E  = __fmaf_rn(xb[i*F_IN + 6], w, E);
        }
        float px2 = __fmul_rn(px,px), py2 = __fmul_rn(py,py), pz2 = __fmul_rn(pz,pz);
        float pt = __fsqrt_rn(__fadd_rn(px2, py2));
        float mass2 = __fsub_rn(__fsub_rn(__fsub_rn(__fmul_rn(E,E), px2), py2), pz2);
        float absp = __fsqrt_rn(__fadd_rn(__fadd_rn(px2, py2), pz2));
        float denom = (absp == 0.f) ? 1.f : absp;
        float cosT  = (absp == 0.f) ? 1.f : __fdiv_rn(pz, denom);
        bool ok = (__fmul_rn(cosT,cosT) < 1.f);
        float ratio = ok ? __fdiv_rn(__fsub_rn(1.f, cosT), __fadd_rn(1.f, cosT)) : 1.f;
        float eta = ok ? __fmul_rn(-0.5f, logf(ratio)) : 0.f;
        float phi = (px == 0.f && py == 0.f) ? 0.f : atan2f(py, px);
        out[b*6+0] = s_x2[0];
        out[b*6+1] = s_x2[1];
        out[b*6+2] = pt;
        out[b*6+3] = eta;
        out[b*6+4] = phi;
        out[b*6+5] = mass2;
    }
}

// ---------------- launch ----------------
extern "C" void kernel_launch(void* const* d_in, const int* in_sizes, int n_in,
                              void* d_out, int out_size) {
    const float* xx    = (const float*)d_in[0];
    const float* emb1  = (const float*)d_in[1];
    const float* emb2  = (const float*)d_in[2];
    const float* emb3  = (const float*)d_in[3];
    const float* mean  = (const float*)d_in[4];
    const float* stdv  = (const float*)d_in[5];
    const float* vmin  = (const float*)d_in[6];
    const float* vmax  = (const float*)d_in[7];
    const float* W0    = (const float*)d_in[8];
    const float* b0    = (const float*)d_in[9];
    const float* Wh    = (const float*)d_in[10];
    const float* bh    = (const float*)d_in[11];
    const float* gamma = (const float*)d_in[12];
    const float* beta  = (const float*)d_in[13];
    const float* mmean = (const float*)d_in[14];
    const float* mvar  = (const float*)d_in[15];
    const float* Wc    = (const float*)d_in[16];
    const float* bc    = (const float*)d_in[17];
    const float* W2    = (const float*)d_in[18];
    const float* b2    = (const float*)d_in[19];
    const float* W100  = (const float*)d_in[20];
    const float* b100  = (const float*)d_in[21];

    float *pG, *pA, *pB;
    cudaGetSymbolAddress((void**)&pG, d_g);
    cudaGetSymbolAddress((void**)&pA, d_hA);
    cudaGetSymbolAddress((void**)&pB, d_hB);

    prep_kernel<<<(B*NP + 255)/256, 256>>>(xx, emb1, emb2, emb3, mean, stdv, vmin, vmax);

    const dim3 GL(NBX, SPLITK);   // (57, 10) = 570 blocks <= 592 co-resident

    for (int it = 0; it < NP; it++) {
        knn_kernel<<<B, 128>>>(Wc, bc, it > 0 ? 1 : 0);

        layer_kernel<<<GL, 256>>>(pG, GDIM, W0, b0,
                                  gamma, beta, mmean, mvar, pA);
        layer_kernel<<<GL, 256>>>(pA, H, Wh + 0*(size_t)H*H, bh + 0*H,
                                  gamma + 1*H, beta + 1*H, mmean + 1*H, mvar + 1*H, pB);
        layer_kernel<<<GL, 256>>>(pB, H, Wh + 1*(size_t)H*H, bh + 1*H,
                                  gamma + 2*H, beta + 2*H, mmean + 2*H, mvar + 2*H, pA);
        layer_kernel<<<GL, 256>>>(pA, H, Wh + 2*(size_t)H*H, bh + 2*H,
                                  gamma + 3*H, beta + 3*H, mmean + 3*H, mvar + 3*H, pB);
        layer_kernel<<<GL, 256>>>(pB, H, Wh + 3*(size_t)H*H, bh + 3*H,
                                  gamma + 4*H, beta + 4*H, mmean + 4*H, mvar + 4*H, pA);
    }

    heads_kernel<<<B, 256>>>(xx, W2, b2, W100, b100, (float*)d_out);
}